// round 1
// baseline (speedup 1.0000x reference)
#include <cuda_runtime.h>
#include <math.h>

#define NRAYS 65536
#define T0V 128
#define T1V 64
#define CCH 16
#define MIN_NEAR 0.05f

__device__ double g_acc[3]; // prop_sum, uni_sum, bi_sum

__device__ __forceinline__ float warp_incl_scan(float x, int lane) {
#pragma unroll
    for (int d = 1; d < 32; d <<= 1) {
        float v = __shfl_up_sync(0xffffffffu, x, d);
        if (lane >= d) x += v;
    }
    return x;
}

__device__ __forceinline__ float warp_sum(float x) {
#pragma unroll
    for (int d = 16; d > 0; d >>= 1) x += __shfl_xor_sync(0xffffffffu, x, d);
    return x;
}

__global__ void __launch_bounds__(128) nerf_init_kernel() {
    if (threadIdx.x < 3) g_acc[threadIdx.x] = 0.0;
}

__global__ void __launch_bounds__(128) nerf_final_kernel(float* out) {
    if (threadIdx.x == 0) {
        double n = (double)NRAYS;
        out[7 * NRAYS]     = (float)(g_acc[0] / (n * (double)T1V));
        out[7 * NRAYS + 1] = (float)(g_acc[1] / (3.0 * n) + 2.0 * g_acc[2] / n);
    }
}

__global__ void __launch_bounds__(128) nerf_main_kernel(
    const float* __restrict__ ro, const float* __restrict__ rdv,
    const float* __restrict__ aabb,
    const float* __restrict__ sc, const float* __restrict__ sf,
    const float* __restrict__ colors,
    const float* __restrict__ wv, const float* __restrict__ bv,
    float* __restrict__ out)
{
    __shared__ float cdf_s[4][130];
    __shared__ float cw1_s[4][130];
    __shared__ float bins1_s[4][66];
    __shared__ float w1_s[4][64];
    __shared__ float s_prop[4], s_uni[4], s_bi[4];

    const int warp = threadIdx.x >> 5;
    const int lane = threadIdx.x & 31;
    const int ray = blockIdx.x * 4 + warp;

    const float ox = ro[3 * ray], oy = ro[3 * ray + 1], oz = ro[3 * ray + 2];
    const float dx = rdv[3 * ray], dy = rdv[3 * ray + 1], dz = rdv[3 * ray + 2];

    // near / far from aabb
    float near, far;
    {
        float tnx = (aabb[0] - ox) / (dx + 1e-15f);
        float tny = (aabb[1] - oy) / (dy + 1e-15f);
        float tnz = (aabb[2] - oz) / (dz + 1e-15f);
        float tfx = (aabb[3] - ox) / (dx + 1e-15f);
        float tfy = (aabb[4] - oy) / (dy + 1e-15f);
        float tfz = (aabb[5] - oz) / (dz + 1e-15f);
        float nmx = fminf(tnx, tfx), nmy = fminf(tny, tfy), nmz = fminf(tnz, tfz);
        float fmx = fmaxf(tnx, tfx), fmy = fmaxf(tny, tfy), fmz = fmaxf(tnz, tfz);
        near = fmaxf(nmx, fmaxf(nmy, nmz));
        far  = fminf(fmx, fminf(fmy, fmz));
        if (far < near) { near = 1e9f; far = 1e9f; }
        near = fmaxf(near, MIN_NEAR);
    }
    const float snear = (near < 1.f) ? near * 0.5f : 1.f - 1.f / (2.f * near);
    const float sfar  = (far  < 1.f) ? far  * 0.5f : 1.f - 1.f / (2.f * far);

    // rb(b) = spacing_inv(snear*(1-b)+sfar*b)
    auto rb = [&](float b) {
        float x = snear * (1.f - b) + sfar * b;
        return (x < 0.5f) ? 2.f * x : 1.f / (2.f - 2.f * x);
    };

    const float inv128 = 0.0078125f;

    // ---------------- coarse pass (4 samples / lane) ----------------
    float4 sc4 = reinterpret_cast<const float4*>(sc + (size_t)ray * T0V)[lane];
    float sg[4] = {sc4.x, sc4.y, sc4.z, sc4.w};
    float e[4], al[4];
    {
        float rbp = rb((float)(4 * lane) * inv128);
#pragma unroll
        for (int q = 0; q < 4; q++) {
            float rbn = rb((float)(4 * lane + q + 1) * inv128);
            e[q] = (rbn - rbp) * sg[q];
            al[q] = 1.f - __expf(-e[q]);
            rbp = rbn;
        }
    }
    float w0v[4];
    {
        float tot = e[0] + e[1] + e[2] + e[3];
        float incl = warp_incl_scan(tot, lane);
        float pre = incl - tot;
#pragma unroll
        for (int q = 0; q < 4; q++) {
            float w = al[q] * __expf(-pre);
            if (!isfinite(w)) w = 0.f;
            w0v[q] = w;
            pre += e[q];
        }
    }
    // cw1: prefix cumsum of w0 (for interlevel)
    {
        float l0 = w0v[0], l1 = l0 + w0v[1], l2 = l1 + w0v[2], l3 = l2 + w0v[3];
        float incl = warp_incl_scan(l3, lane);
        float excl = incl - l3;
        cw1_s[warp][4 * lane + 1] = excl + l0;
        cw1_s[warp][4 * lane + 2] = excl + l1;
        cw1_s[warp][4 * lane + 3] = excl + l2;
        cw1_s[warp][4 * lane + 4] = excl + l3;
        if (lane == 0) cw1_s[warp][0] = 0.f;
    }
    // cdf of (w0+0.01)
    {
        float p0 = w0v[0] + 0.01f, p1 = w0v[1] + 0.01f, p2 = w0v[2] + 0.01f, p3 = w0v[3] + 0.01f;
        float l0 = p0, l1 = l0 + p1, l2 = l1 + p2, l3 = l2 + p3;
        float incl = warp_incl_scan(l3, lane);
        float excl = incl - l3;
        float total = __shfl_sync(0xffffffffu, incl, 31);
        float invt = 1.f / total;
        cdf_s[warp][4 * lane + 1] = fminf((excl + l0) * invt, 1.f);
        cdf_s[warp][4 * lane + 2] = fminf((excl + l1) * invt, 1.f);
        cdf_s[warp][4 * lane + 3] = fminf((excl + l2) * invt, 1.f);
        cdf_s[warp][4 * lane + 4] = fminf((excl + l3) * invt, 1.f);
        if (lane == 0) cdf_s[warp][0] = 0.f;
    }
    __syncwarp();

    // ---------------- sample_pdf: 65 inverse-CDF queries ----------------
    for (int j = lane; j < 65; j += 32) {
        float u = ((float)j + 0.5f) * (1.0f / 65.0f);
        int lo = 0, hi = 129;
        while (lo < hi) {
            int mid = (lo + hi) >> 1;
            if (cdf_s[warp][mid] <= u) lo = mid + 1; else hi = mid;
        }
        int below = lo - 1; if (below < 0) below = 0; if (below > 128) below = 128;
        int above = lo;     if (above > 128) above = 128;
        float c0 = cdf_s[warp][below], c1 = cdf_s[warp][above];
        float dd = c1 - c0;
        float t = (dd > 0.f) ? fminf(fmaxf((u - c0) / dd, 0.f), 1.f)
                             : ((u > c0) ? 1.f : 0.f);
        float b0v = (float)below * inv128, b1v = (float)above * inv128;
        bins1_s[warp][j] = b0v + t * (b1v - b0v);
    }
    __syncwarp();

    // ---------------- fine pass (2 samples / lane) ----------------
    const int t0i = 2 * lane;
    float bA = bins1_s[warp][t0i], bB = bins1_s[warp][t0i + 1], bC = bins1_s[warp][t0i + 2];
    float rA = rb(bA), rB = rb(bB), rC = rb(bC);
    float2 sf2 = reinterpret_cast<const float2*>(sf + (size_t)ray * T1V)[lane];
    float ef0 = (rB - rA) * sf2.x;
    float ef1 = (rC - rB) * sf2.y;
    float a0 = 1.f - __expf(-ef0);
    float a1 = 1.f - __expf(-ef1);
    float w1a, w1b;
    {
        float tot = ef0 + ef1;
        float incl = warp_incl_scan(tot, lane);
        float excl = incl - tot;
        w1a = a0 * __expf(-excl);
        w1b = a1 * __expf(-(excl + ef0));
        if (!isfinite(w1a)) w1a = 0.f;
        if (!isfinite(w1b)) w1b = 0.f;
    }
    w1_s[warp][t0i] = w1a;
    w1_s[warp][t0i + 1] = w1b;

    float rt0 = 0.5f * (rA + rB), rt1 = 0.5f * (rB + rC);
    float wsum_p = w1a + w1b;
    float depth_p = w1a * rt0 + w1b * rt1;

    // contracted positions
    float fx_p = 0.f, fy_p = 0.f, fz_p = 0.f;
#pragma unroll
    for (int q = 0; q < 2; q++) {
        float rt = (q == 0) ? rt0 : rt1;
        float w  = (q == 0) ? w1a : w1b;
        float px = ox + dx * rt, py = oy + dy * rt, pz = oz + dz * rt;
        float ax = fabsf(px), ay = fabsf(py), az = fabsf(pz);
        float mag = fmaxf(ax, fmaxf(ay, az));
        if (mag >= 1.f) {
            float inv = 1.f / mag;
            float smax = (2.f - inv) * inv;
            int idx = (ax >= ay && ax >= az) ? 0 : ((ay >= az) ? 1 : 2);
            px *= (idx == 0) ? smax : inv;
            py *= (idx == 1) ? smax : inv;
            pz *= (idx == 2) ? smax : inv;
        }
        fx_p += w * px; fy_p += w * py; fz_p += w * pz;
    }

    // distortion loss parts
    float i0 = bB - bA, i1 = bC - bB;
    float m0 = bA + 0.5f * i0, m1 = bB + 0.5f * i1;
    float uni_p = i0 * w1a * w1a + i1 * w1b * w1b;
    float wm0 = w1a * m0, wm1 = w1b * m1;
    float bi_p;
    {
        float wt = w1a + w1b;
        float winc = warp_incl_scan(wt, lane);
        float wex = winc - wt;
        float mt = wm0 + wm1;
        float minc = warp_incl_scan(mt, lane);
        float mex = minc - mt;
        bi_p = wm0 * wex - w1a * mex + wm1 * (wex + w1a) - w1b * (mex + wm0);
    }

    // interlevel loss parts (analytic searchsorted on uniform bins0)
    float prop_p;
    {
        int il0 = min((int)floorf(bA * 128.f), 127); if (il0 < 0) il0 = 0;
        int ih0 = min((int)floorf(bB * 128.f), 127); if (ih0 < 0) ih0 = 0;
        int il1 = min((int)floorf(bB * 128.f), 127); if (il1 < 0) il1 = 0;
        int ih1 = min((int)floorf(bC * 128.f), 127); if (ih1 < 0) ih1 = 0;
        float ww0 = cw1_s[warp][ih0 + 1] - cw1_s[warp][il0];
        float ww1 = cw1_s[warp][ih1 + 1] - cw1_s[warp][il1];
        float e0l = fmaxf(w1a - ww0, 0.f);
        float e1l = fmaxf(w1b - ww1, 0.f);
        prop_p = e0l * e0l / (w1a + 1e-8f) + e1l * e1l / (w1b + 1e-8f);
    }
    __syncwarp();

    // ---------------- colors: f_image reduction ----------------
    float4 acc = make_float4(0.f, 0.f, 0.f, 0.f);
    const float4* cptr = reinterpret_cast<const float4*>(colors + (size_t)ray * (T1V * CCH));
#pragma unroll
    for (int k = 0; k < 8; k++) {
        int idx4 = lane + 32 * k;
        float4 c4 = cptr[idx4];
        float w = w1_s[warp][idx4 >> 2];
        acc.x += w * c4.x; acc.y += w * c4.y; acc.z += w * c4.z; acc.w += w * c4.w;
    }
#pragma unroll
    for (int d = 4; d <= 16; d <<= 1) {
        acc.x += __shfl_xor_sync(0xffffffffu, acc.x, d);
        acc.y += __shfl_xor_sync(0xffffffffu, acc.y, d);
        acc.z += __shfl_xor_sync(0xffffffffu, acc.z, d);
        acc.w += __shfl_xor_sync(0xffffffffu, acc.w, d);
    }
    // matvec with w_view [16,3]
    int cg = lane & 3;
    float lg0, lg1, lg2;
    {
        int cbase = 4 * cg;
        lg0 = acc.x * wv[(cbase + 0) * 3 + 0] + acc.y * wv[(cbase + 1) * 3 + 0]
            + acc.z * wv[(cbase + 2) * 3 + 0] + acc.w * wv[(cbase + 3) * 3 + 0];
        lg1 = acc.x * wv[(cbase + 0) * 3 + 1] + acc.y * wv[(cbase + 1) * 3 + 1]
            + acc.z * wv[(cbase + 2) * 3 + 1] + acc.w * wv[(cbase + 3) * 3 + 1];
        lg2 = acc.x * wv[(cbase + 0) * 3 + 2] + acc.y * wv[(cbase + 1) * 3 + 2]
            + acc.z * wv[(cbase + 2) * 3 + 2] + acc.w * wv[(cbase + 3) * 3 + 2];
#pragma unroll
        for (int d = 1; d <= 2; d <<= 1) {
            lg0 += __shfl_xor_sync(0xffffffffu, lg0, d);
            lg1 += __shfl_xor_sync(0xffffffffu, lg1, d);
            lg2 += __shfl_xor_sync(0xffffffffu, lg2, d);
        }
    }

    // ---------------- reductions & outputs ----------------
    float wsum  = warp_sum(wsum_p);
    float depth = warp_sum(depth_p);
    float fx = warp_sum(fx_p);
    float fy = warp_sum(fy_p);
    float fz = warp_sum(fz_p);
    float prop = warp_sum(prop_p);
    float uni  = warp_sum(uni_p);
    float bi   = warp_sum(bi_p);

    if (lane == 0) {
        float bg = 1.f - wsum;
        float im0 = 1.f / (1.f + __expf(-(lg0 + bv[0]))) + bg;
        float im1 = 1.f / (1.f + __expf(-(lg1 + bv[1]))) + bg;
        float im2 = 1.f / (1.f + __expf(-(lg2 + bv[2]))) + bg;
        out[3 * ray + 0] = im0;
        out[3 * ray + 1] = im1;
        out[3 * ray + 2] = im2;
        out[3 * NRAYS + ray] = depth;
        out[4 * NRAYS + 3 * ray + 0] = fx;
        out[4 * NRAYS + 3 * ray + 1] = fy;
        out[4 * NRAYS + 3 * ray + 2] = fz;
        s_prop[warp] = prop; s_uni[warp] = uni; s_bi[warp] = bi;
    }
    __syncthreads();
    if (threadIdx.x == 0) {
        double p = (double)s_prop[0] + s_prop[1] + s_prop[2] + s_prop[3];
        double u = (double)s_uni[0]  + s_uni[1]  + s_uni[2]  + s_uni[3];
        double b = (double)s_bi[0]   + s_bi[1]   + s_bi[2]   + s_bi[3];
        atomicAdd(&g_acc[0], p);
        atomicAdd(&g_acc[1], u);
        atomicAdd(&g_acc[2], b);
    }
}

extern "C" void kernel_launch(void* const* d_in, const int* in_sizes, int n_in,
                              void* d_out, int out_size) {
    const float* rays_o = (const float*)d_in[0];
    const float* rays_d = (const float*)d_in[1];
    const float* aabb   = (const float*)d_in[2];
    const float* sc     = (const float*)d_in[3];
    const float* sf     = (const float*)d_in[4];
    const float* colors = (const float*)d_in[5];
    const float* wv     = (const float*)d_in[6];
    const float* bv     = (const float*)d_in[7];
    float* out = (float*)d_out;

    nerf_init_kernel<<<1, 128>>>();
    nerf_main_kernel<<<NRAYS / 4, 128>>>(rays_o, rays_d, aabb, sc, sf, colors, wv, bv, out);
    nerf_final_kernel<<<1, 128>>>(out);
}